// round 14
// baseline (speedup 1.0000x reference)
#include <cuda_runtime.h>
#include <float.h>

// ChamferLossKL: bs=8, n=2048, d=4. Single fused kernel.
// t_ij = S_ij + csb_j + ca_i = 2*KL_ij + 4  (> 0 since KL >= 0), once per pair.
//   S = sum_d A_id*iv_jd + sum_d mu_id*w_jd
//   A = exp(la)+mu_a^2, ca = -sum(la); iv = exp(-lb), w = -2*mu_b*iv,
//   csb = sum(mu_b^2*iv) + sum(lb)
// loss_b = 0.5*(sum_i min_j t + sum_j min_i t) - 4*NP
// Positivity => raw float bits are order-isomorphic to values: redux.min.u32
// and atomicMax(~bits) (zero identity) work on raw bits, no key transform.
// R14: each chain split into two independent 4-deep FFMA2 halves
// (seeded ca / csb), merged by one FADD2 — dep depth 9 -> 5, same op count.

#define NB 8
#define NP 2048
#define ITILE 512           // i per CTA (4 per thread)
#define NITILE 4
#define CHJ 64              // j per CTA
#define CHP 32              // j-pairs per CTA
#define NCH 32
#define CTAS_PER_B (NITILE * NCH)   // 128

typedef unsigned long long ull;

__device__ __forceinline__ ull ffma2(ull a, ull b, ull c) {
    ull d; asm("fma.rn.f32x2 %0, %1, %2, %3;" : "=l"(d) : "l"(a), "l"(b), "l"(c));
    return d;
}
__device__ __forceinline__ ull fadd2(ull a, ull b) {
    ull d; asm("add.rn.f32x2 %0, %1, %2;" : "=l"(d) : "l"(a), "l"(b));
    return d;
}
__device__ __forceinline__ ull packdup(float x) {
    ull d; asm("mov.b64 %0, {%1, %1};" : "=l"(d) : "f"(x));
    return d;
}
__device__ __forceinline__ void unpk(ull v, float& lo, float& hi) {
    asm("mov.b64 {%0, %1}, %2;" : "=f"(lo), "=f"(hi) : "l"(v));
}
__device__ __forceinline__ void lds_v2(ull& a, ull& b, unsigned int addr) {
    asm volatile("ld.shared.v2.u64 {%0, %1}, [%2];" : "=l"(a), "=l"(b) : "r"(addr));
}
__device__ __forceinline__ ull lds_1(unsigned int addr) {
    ull a; asm volatile("ld.shared.u64 %0, [%1];" : "=l"(a) : "r"(addr));
    return a;
}
__device__ __forceinline__ unsigned int redux_umin(unsigned int v) {
    unsigned int r;
    asm("redux.sync.min.u32 %0, %1, 0xffffffff;" : "=r"(r) : "r"(v));
    return r;
}

// ~rawbits min accumulators for positive floats (zero = identity)
__device__ unsigned int g_rowk[NB * NP];   // 64 KB, static zero-init
__device__ unsigned int g_colk[NB * NP];   // 64 KB, static zero-init
__device__ unsigned int g_done[NB];        // arrival counters, zero-init

// grid (NITILE, NB, NCH) = 1024 CTAs, 128 threads.
__global__ __launch_bounds__(128, 6) void ck_main(const float* __restrict__ mu_p,
                                                  const float* __restrict__ lv_p,
                                                  const float* __restrict__ mu_g,
                                                  const float* __restrict__ lv_g,
                                                  float* __restrict__ out) {
    __shared__ float4 s_stream[CHP * 5];  // 2.5 KB
    __shared__ uint2  s_col[4 * CHP];     // 1 KB (raw-bit mins)
    __shared__ unsigned int s_last;

    int tid  = threadIdx.x;
    int lane = tid & 31;
    int w    = tid >> 5;
    int b     = blockIdx.y;
    int itile = blockIdx.x;
    int ch    = blockIdx.z;

    // ---- self coefficients: four i per thread ----
    int i0 = itile * ITILE + tid;
    ull cfA[4][4], cfM[4][4], cfC[4];
#pragma unroll
    for (int c = 0; c < 4; c++) {
        int i = i0 + c * 128;
        float4 mp = reinterpret_cast<const float4*>(mu_p)[b * NP + i];
        float4 lp = reinterpret_cast<const float4*>(lv_p)[b * NP + i];
        cfA[c][0] = packdup(__expf(lp.x) + mp.x * mp.x);
        cfA[c][1] = packdup(__expf(lp.y) + mp.y * mp.y);
        cfA[c][2] = packdup(__expf(lp.z) + mp.z * mp.z);
        cfA[c][3] = packdup(__expf(lp.w) + mp.w * mp.w);
        cfM[c][0] = packdup(mp.x); cfM[c][1] = packdup(mp.y);
        cfM[c][2] = packdup(mp.z); cfM[c][3] = packdup(mp.w);
        cfC[c]    = packdup(-(lp.x + lp.y + lp.z + lp.w));
    }

    // ---- stream prep (gts): threads 0..31 build one j-pair each ----
    if (tid < CHP) {
        int j0 = ch * CHJ + 2 * tid;
        float4 mg0 = reinterpret_cast<const float4*>(mu_g)[b * NP + j0];
        float4 lg0 = reinterpret_cast<const float4*>(lv_g)[b * NP + j0];
        float4 mg1 = reinterpret_cast<const float4*>(mu_g)[b * NP + j0 + 1];
        float4 lg1 = reinterpret_cast<const float4*>(lv_g)[b * NP + j0 + 1];
        float4 iv0, iv1, w0, w1;
        iv0.x = __expf(-lg0.x); iv0.y = __expf(-lg0.y);
        iv0.z = __expf(-lg0.z); iv0.w = __expf(-lg0.w);
        iv1.x = __expf(-lg1.x); iv1.y = __expf(-lg1.y);
        iv1.z = __expf(-lg1.z); iv1.w = __expf(-lg1.w);
        w0.x = -2.f * mg0.x * iv0.x; w0.y = -2.f * mg0.y * iv0.y;
        w0.z = -2.f * mg0.z * iv0.z; w0.w = -2.f * mg0.w * iv0.w;
        w1.x = -2.f * mg1.x * iv1.x; w1.y = -2.f * mg1.y * iv1.y;
        w1.z = -2.f * mg1.z * iv1.z; w1.w = -2.f * mg1.w * iv1.w;
        float csb0 = mg0.x * mg0.x * iv0.x + mg0.y * mg0.y * iv0.y
                   + mg0.z * mg0.z * iv0.z + mg0.w * mg0.w * iv0.w
                   + lg0.x + lg0.y + lg0.z + lg0.w;
        float csb1 = mg1.x * mg1.x * iv1.x + mg1.y * mg1.y * iv1.y
                   + mg1.z * mg1.z * iv1.z + mg1.w * mg1.w * iv1.w
                   + lg1.x + lg1.y + lg1.z + lg1.w;
        s_stream[tid * 5 + 0] = make_float4(iv0.x, iv1.x, iv0.y, iv1.y);
        s_stream[tid * 5 + 1] = make_float4(iv0.z, iv1.z, iv0.w, iv1.w);
        s_stream[tid * 5 + 2] = make_float4(w0.x, w1.x, w0.y, w1.y);
        s_stream[tid * 5 + 3] = make_float4(w0.z, w1.z, w0.w, w1.w);
        s_stream[tid * 5 + 4] = make_float4(csb0, csb1, 0.f, 0.f);
    }
    __syncthreads();

    unsigned int sbase = (unsigned int)__cvta_generic_to_shared(s_stream);
    float rmin[4][2];
#pragma unroll
    for (int c = 0; c < 4; c++) { rmin[c][0] = FLT_MAX; rmin[c][1] = FLT_MAX; }

    unsigned int ad = sbase;
#pragma unroll 4
    for (int p = 0; p < CHP; p++) {
        ull q0, q1, q2, q3, r0, r1, r2, r3;
        lds_v2(q0, q1, ad);
        lds_v2(q2, q3, ad + 16);
        lds_v2(r0, r1, ad + 32);
        lds_v2(r2, r3, ad + 48);
        ull csb = lds_1(ad + 64);

        float tl[4], th[4];
#pragma unroll
        for (int c = 0; c < 4; c++) {
            // two independent 4-deep halves (dep depth 5 total)
            ull s1 = ffma2(cfA[c][0], q0, cfC[c]);
            ull s2 = ffma2(cfM[c][0], r0, csb);
            s1 = ffma2(cfA[c][1], q1, s1);
            s2 = ffma2(cfM[c][1], r1, s2);
            s1 = ffma2(cfA[c][2], q2, s1);
            s2 = ffma2(cfM[c][2], r2, s2);
            s1 = ffma2(cfA[c][3], q3, s1);
            s2 = ffma2(cfM[c][3], r3, s2);
            ull t = fadd2(s1, s2);
            unpk(t, tl[c], th[c]);
            rmin[c][0] = fminf(rmin[c][0], tl[c]);
            rmin[c][1] = fminf(rmin[c][1], th[c]);
        }
        float clo = fminf(fminf(tl[0], tl[1]), fminf(tl[2], tl[3]));
        float chi = fminf(fminf(th[0], th[1]), fminf(th[2], th[3]));
        unsigned int k0 = redux_umin(__float_as_uint(clo));
        unsigned int k1 = redux_umin(__float_as_uint(chi));
        if (lane == 0) s_col[w * CHP + p] = make_uint2(k0, k1);
        ad += 80;
    }

    // row mins -> ~rawbits atomicMax (32 contenders per address)
#pragma unroll
    for (int c = 0; c < 4; c++) {
        float m = fminf(rmin[c][0], rmin[c][1]);
        atomicMax(&g_rowk[b * NP + i0 + c * 128], ~__float_as_uint(m));
    }

    __syncthreads();
    if (tid < CHP) {
        uint2 m0 = s_col[tid], m1 = s_col[CHP + tid];
        uint2 m2 = s_col[2 * CHP + tid], m3 = s_col[3 * CHP + tid];
        unsigned int kx = min(min(m0.x, m1.x), min(m2.x, m3.x));
        unsigned int ky = min(min(m0.y, m1.y), min(m2.y, m3.y));
        int j0 = ch * CHJ + 2 * tid;
        atomicMax(&g_colk[b * NP + j0],     ~kx);
        atomicMax(&g_colk[b * NP + j0 + 1], ~ky);
    }

    // ---- fused tail: last CTA of this batch reduces + resets ----
    __threadfence();
    if (tid == 0) {
        unsigned int old = atomicAdd(&g_done[b], 1u);
        s_last = (old == CTAS_PER_B - 1) ? 1u : 0u;
    }
    __syncthreads();
    if (s_last) {
        __threadfence();  // acquire: all batch-b key writes visible
        float sum = 0.f;
#pragma unroll
        for (int k = 0; k < NP / 128; k++) {   // 16 iters, 128 thr
            int idx = b * NP + k * 128 + tid;
            unsigned int rk = g_rowk[idx];
            unsigned int ck = g_colk[idx];
            sum += __uint_as_float(~rk) + __uint_as_float(~ck);
            g_rowk[idx] = 0u;   // reset for next graph replay
            g_colk[idx] = 0u;
        }
        __shared__ float red[128];
        red[tid] = sum;
        __syncthreads();
        for (int st = 64; st > 0; st >>= 1) {
            if (tid < st) red[tid] += red[tid + st];
            __syncthreads();
        }
        if (tid == 0) {
            out[b] = 0.5f * red[0] - 2.0f * (2.0f * NP);
            g_done[b] = 0u;     // reset counter
        }
    }
}

extern "C" void kernel_launch(void* const* d_in, const int* in_sizes, int n_in,
                              void* d_out, int out_size) {
    const float* mu_p = (const float*)d_in[0];
    const float* lv_p = (const float*)d_in[1];
    const float* mu_g = (const float*)d_in[2];
    const float* lv_g = (const float*)d_in[3];
    float* out = (float*)d_out;

    dim3 grid(NITILE, NB, NCH);  // 4 x 8 x 32 = 1024 CTAs
    ck_main<<<grid, 128>>>(mu_p, lv_p, mu_g, lv_g, out);
}

// round 15
// speedup vs baseline: 1.0153x; 1.0153x over previous
#include <cuda_runtime.h>
#include <float.h>

// ChamferLossKL: bs=8, n=2048, d=4. Single fused kernel.
// t_ij = S_ij + csb_j + ca_i = 2*KL_ij + 4  (> 0 since KL >= 0), once per pair.
//   S = sum_d A_id*iv_jd + sum_d mu_id*w_jd
//   A = exp(la)+mu_a^2, ca = -sum(la); iv = exp(-lb), w = -2*mu_b*iv,
//   csb = sum(mu_b^2*iv) + sum(lb)
// loss_b = 0.5*(sum_i min_j t + sum_j min_i t) - 4*NP
// Positivity => raw float bits are order-isomorphic: redux.min.u32 and
// atomicMax(~bits) (zero identity) on raw bits.
// R15: 2 i-chains (~60 regs) + __launch_bounds__(128,8) so all 1024 CTAs
// are resident in ONE wave (8/SM cap, ~7/SM actual) — kills the 136-CTA
// straggler wave that pinned R11-R14 at ~22.5us.

#define NB 8
#define NP 2048
#define ITILE 256           // i per CTA (2 per thread)
#define NITILE 8
#define CHJ 128             // j per CTA
#define CHP 64              // j-pairs per CTA
#define NCH 16
#define CTAS_PER_B (NITILE * NCH)   // 128

typedef unsigned long long ull;

__device__ __forceinline__ ull ffma2(ull a, ull b, ull c) {
    ull d; asm("fma.rn.f32x2 %0, %1, %2, %3;" : "=l"(d) : "l"(a), "l"(b), "l"(c));
    return d;
}
__device__ __forceinline__ ull fadd2(ull a, ull b) {
    ull d; asm("add.rn.f32x2 %0, %1, %2;" : "=l"(d) : "l"(a), "l"(b));
    return d;
}
__device__ __forceinline__ ull packdup(float x) {
    ull d; asm("mov.b64 %0, {%1, %1};" : "=l"(d) : "f"(x));
    return d;
}
__device__ __forceinline__ void unpk(ull v, float& lo, float& hi) {
    asm("mov.b64 {%0, %1}, %2;" : "=f"(lo), "=f"(hi) : "l"(v));
}
__device__ __forceinline__ void lds_v2(ull& a, ull& b, unsigned int addr) {
    asm volatile("ld.shared.v2.u64 {%0, %1}, [%2];" : "=l"(a), "=l"(b) : "r"(addr));
}
__device__ __forceinline__ ull lds_1(unsigned int addr) {
    ull a; asm volatile("ld.shared.u64 %0, [%1];" : "=l"(a) : "r"(addr));
    return a;
}
__device__ __forceinline__ unsigned int redux_umin(unsigned int v) {
    unsigned int r;
    asm("redux.sync.min.u32 %0, %1, 0xffffffff;" : "=r"(r) : "r"(v));
    return r;
}

// ~rawbits min accumulators for positive floats (zero = identity)
__device__ unsigned int g_rowk[NB * NP];   // 64 KB, static zero-init
__device__ unsigned int g_colk[NB * NP];   // 64 KB, static zero-init
__device__ unsigned int g_done[NB];        // arrival counters, zero-init

// grid (NITILE, NB, NCH) = 1024 CTAs, 128 threads, 8 CTAs/SM -> 1 wave.
__global__ __launch_bounds__(128, 8) void ck_main(const float* __restrict__ mu_p,
                                                  const float* __restrict__ lv_p,
                                                  const float* __restrict__ mu_g,
                                                  const float* __restrict__ lv_g,
                                                  float* __restrict__ out) {
    __shared__ float4 s_stream[CHP * 5];  // 5 KB
    __shared__ uint2  s_col[4 * CHP];     // 2 KB (raw-bit mins)
    __shared__ unsigned int s_last;

    int tid  = threadIdx.x;
    int lane = tid & 31;
    int w    = tid >> 5;
    int b     = blockIdx.y;
    int itile = blockIdx.x;
    int ch    = blockIdx.z;

    // ---- self coefficients: two i per thread ----
    int i0 = itile * ITILE + tid;
    ull cfA[2][4], cfM[2][4], cfC[2];
#pragma unroll
    for (int c = 0; c < 2; c++) {
        int i = i0 + c * 128;
        float4 mp = reinterpret_cast<const float4*>(mu_p)[b * NP + i];
        float4 lp = reinterpret_cast<const float4*>(lv_p)[b * NP + i];
        cfA[c][0] = packdup(__expf(lp.x) + mp.x * mp.x);
        cfA[c][1] = packdup(__expf(lp.y) + mp.y * mp.y);
        cfA[c][2] = packdup(__expf(lp.z) + mp.z * mp.z);
        cfA[c][3] = packdup(__expf(lp.w) + mp.w * mp.w);
        cfM[c][0] = packdup(mp.x); cfM[c][1] = packdup(mp.y);
        cfM[c][2] = packdup(mp.z); cfM[c][3] = packdup(mp.w);
        cfC[c]    = packdup(-(lp.x + lp.y + lp.z + lp.w));
    }

    // ---- stream prep (gts): threads 0..63 build one j-pair each ----
    if (tid < CHP) {
        int j0 = ch * CHJ + 2 * tid;
        float4 mg0 = reinterpret_cast<const float4*>(mu_g)[b * NP + j0];
        float4 lg0 = reinterpret_cast<const float4*>(lv_g)[b * NP + j0];
        float4 mg1 = reinterpret_cast<const float4*>(mu_g)[b * NP + j0 + 1];
        float4 lg1 = reinterpret_cast<const float4*>(lv_g)[b * NP + j0 + 1];
        float4 iv0, iv1, w0, w1;
        iv0.x = __expf(-lg0.x); iv0.y = __expf(-lg0.y);
        iv0.z = __expf(-lg0.z); iv0.w = __expf(-lg0.w);
        iv1.x = __expf(-lg1.x); iv1.y = __expf(-lg1.y);
        iv1.z = __expf(-lg1.z); iv1.w = __expf(-lg1.w);
        w0.x = -2.f * mg0.x * iv0.x; w0.y = -2.f * mg0.y * iv0.y;
        w0.z = -2.f * mg0.z * iv0.z; w0.w = -2.f * mg0.w * iv0.w;
        w1.x = -2.f * mg1.x * iv1.x; w1.y = -2.f * mg1.y * iv1.y;
        w1.z = -2.f * mg1.z * iv1.z; w1.w = -2.f * mg1.w * iv1.w;
        float csb0 = mg0.x * mg0.x * iv0.x + mg0.y * mg0.y * iv0.y
                   + mg0.z * mg0.z * iv0.z + mg0.w * mg0.w * iv0.w
                   + lg0.x + lg0.y + lg0.z + lg0.w;
        float csb1 = mg1.x * mg1.x * iv1.x + mg1.y * mg1.y * iv1.y
                   + mg1.z * mg1.z * iv1.z + mg1.w * mg1.w * iv1.w
                   + lg1.x + lg1.y + lg1.z + lg1.w;
        s_stream[tid * 5 + 0] = make_float4(iv0.x, iv1.x, iv0.y, iv1.y);
        s_stream[tid * 5 + 1] = make_float4(iv0.z, iv1.z, iv0.w, iv1.w);
        s_stream[tid * 5 + 2] = make_float4(w0.x, w1.x, w0.y, w1.y);
        s_stream[tid * 5 + 3] = make_float4(w0.z, w1.z, w0.w, w1.w);
        s_stream[tid * 5 + 4] = make_float4(csb0, csb1, 0.f, 0.f);
    }
    __syncthreads();

    unsigned int sbase = (unsigned int)__cvta_generic_to_shared(s_stream);
    float rmin[2][2];
#pragma unroll
    for (int c = 0; c < 2; c++) { rmin[c][0] = FLT_MAX; rmin[c][1] = FLT_MAX; }

    unsigned int ad = sbase;
#pragma unroll 4
    for (int p = 0; p < CHP; p++) {
        ull q0, q1, q2, q3, r0, r1, r2, r3;
        lds_v2(q0, q1, ad);
        lds_v2(q2, q3, ad + 16);
        lds_v2(r0, r1, ad + 32);
        lds_v2(r2, r3, ad + 48);
        ull csb = lds_1(ad + 64);

        float tl[2], th[2];
#pragma unroll
        for (int c = 0; c < 2; c++) {
            ull s = ffma2(cfA[c][0], q0, cfC[c]);
            s = ffma2(cfA[c][1], q1, s);
            s = ffma2(cfA[c][2], q2, s);
            s = ffma2(cfA[c][3], q3, s);
            s = ffma2(cfM[c][0], r0, s);
            s = ffma2(cfM[c][1], r1, s);
            s = ffma2(cfM[c][2], r2, s);
            s = ffma2(cfM[c][3], r3, s);
            ull t = fadd2(s, csb);
            unpk(t, tl[c], th[c]);
            rmin[c][0] = fminf(rmin[c][0], tl[c]);
            rmin[c][1] = fminf(rmin[c][1], th[c]);
        }
        float clo = fminf(tl[0], tl[1]);
        float chi = fminf(th[0], th[1]);
        unsigned int k0 = redux_umin(__float_as_uint(clo));
        unsigned int k1 = redux_umin(__float_as_uint(chi));
        if (lane == 0) s_col[w * CHP + p] = make_uint2(k0, k1);
        ad += 80;
    }

    // row mins -> ~rawbits atomicMax (16 contenders per address)
#pragma unroll
    for (int c = 0; c < 2; c++) {
        float m = fminf(rmin[c][0], rmin[c][1]);
        atomicMax(&g_rowk[b * NP + i0 + c * 128], ~__float_as_uint(m));
    }

    __syncthreads();
    if (tid < CHP) {
        uint2 m0 = s_col[tid], m1 = s_col[CHP + tid];
        uint2 m2 = s_col[2 * CHP + tid], m3 = s_col[3 * CHP + tid];
        unsigned int kx = min(min(m0.x, m1.x), min(m2.x, m3.x));
        unsigned int ky = min(min(m0.y, m1.y), min(m2.y, m3.y));
        int j0 = ch * CHJ + 2 * tid;
        atomicMax(&g_colk[b * NP + j0],     ~kx);
        atomicMax(&g_colk[b * NP + j0 + 1], ~ky);
    }

    // ---- fused tail: last CTA of this batch reduces + resets ----
    __threadfence();
    if (tid == 0) {
        unsigned int old = atomicAdd(&g_done[b], 1u);
        s_last = (old == CTAS_PER_B - 1) ? 1u : 0u;
    }
    __syncthreads();
    if (s_last) {
        __threadfence();  // acquire: all batch-b key writes visible
        float sum = 0.f;
#pragma unroll
        for (int k = 0; k < NP / 128; k++) {   // 16 iters, 128 thr
            int idx = b * NP + k * 128 + tid;
            unsigned int rk = g_rowk[idx];
            unsigned int ck = g_colk[idx];
            sum += __uint_as_float(~rk) + __uint_as_float(~ck);
            g_rowk[idx] = 0u;   // reset for next graph replay
            g_colk[idx] = 0u;
        }
        __shared__ float red[128];
        red[tid] = sum;
        __syncthreads();
        for (int st = 64; st > 0; st >>= 1) {
            if (tid < st) red[tid] += red[tid + st];
            __syncthreads();
        }
        if (tid == 0) {
            out[b] = 0.5f * red[0] - 2.0f * (2.0f * NP);
            g_done[b] = 0u;     // reset counter
        }
    }
}

extern "C" void kernel_launch(void* const* d_in, const int* in_sizes, int n_in,
                              void* d_out, int out_size) {
    const float* mu_p = (const float*)d_in[0];
    const float* lv_p = (const float*)d_in[1];
    const float* mu_g = (const float*)d_in[2];
    const float* lv_g = (const float*)d_in[3];
    float* out = (float*)d_out;

    dim3 grid(NITILE, NB, NCH);  // 8 x 8 x 16 = 1024 CTAs
    ck_main<<<grid, 128>>>(mu_p, lv_p, mu_g, lv_g, out);
}